// round 11
// baseline (speedup 1.0000x reference)
#include <cuda_runtime.h>

// ---------------- problem constants ----------------
#define NXg 256
#define NYg 256
#define NG  (NXg*NYg)

// tile: interior 16(x) x 32(y), halo 8 -> ext 32x48; 2 RK4 steps per barrier
#define IXt 16
#define IYt 32
#define Hh  8
#define EXt 32
#define EYt 48
#define SW  3              // cells per y-strip
#define NSTR (EYt/SW)      // 16 strips per x-row
#define NSTRIPS (EXt*NSTR) // 512 == NT
#define EYtP 64            // padded slots per x-row (16 strips * 4)
#define EXTP (EXt*EYtP)    // 2048
#define NT  512
#define NBX (NYg/IYt)      // 8
#define NBY (NXg/IXt)      // 16
#define NCTA (NBX*NBY)     // 128 CTAs <= 148 SMs -> co-resident
#define RELAX 100
#define TSTEPS 1024
#define NPAIRS ((RELAX+TSTEPS)/2)   // 562

#define DYN_SMEM (2*3*EXTP*4)       // SA+SB, 49152 bytes

// ---------------- device state ----------------
__device__ float g_m[2][3*NG];   // ping-pong exchange state (per PAIR)
__device__ unsigned g_count;     // monotonic arrival counter
__device__ unsigned g_ibar;      // init barrier counter (self-resetting)
__device__ unsigned g_isense;    // init barrier sense (2 flips/run -> replay-safe)

__device__ __forceinline__ void initbar(unsigned& lsense)
{
    __syncthreads();
    if (threadIdx.x == 0) {
        unsigned s = lsense ^ 1u;
        lsense = s;
        unsigned old;
        asm volatile("atom.add.acq_rel.gpu.u32 %0, [%1], 1;"
                     : "=r"(old) : "l"(&g_ibar) : "memory");
        if (old == NCTA - 1u) {
            asm volatile("st.relaxed.gpu.u32 [%0], %1;" :: "l"(&g_ibar), "r"(0u) : "memory");
            asm volatile("st.release.gpu.u32 [%0], %1;" :: "l"(&g_isense), "r"(s) : "memory");
        } else {
            unsigned v;
            do {
                asm volatile("ld.acquire.gpu.u32 %0, [%1];" : "=r"(v) : "l"(&g_isense) : "memory");
            } while (v != s);
        }
    }
    __syncthreads();
}

// max RK substage (1..8) at which a strip must still be computed.
// -1 = no in-domain cell (dead). Rule per cell (validated R2/R10): an ext
// edge shrinks the valid region only if that edge is interior to the domain.
__device__ __forceinline__ int strip_cap(int ex, int sy, int gx0, int gy0)
{
    int gx = gx0 + ex;
    int cap = -1;
    #pragma unroll
    for (int j = 0; j < SW; j++) {
        int ey = SW*sy + j;
        int gy = gy0 + ey;
        if (gx < 0 || gx >= NXg || gy < 0 || gy >= NYg) continue;
        int c = 8;
        if (gx0 >= 0)         c = min(c, ex);
        if (gx0 + EXt <= NXg) c = min(c, EXt - 1 - ex);
        if (gy0 >= 0)         c = min(c, ey);
        if (gy0 + EYt <= NYg) c = min(c, EYt - 1 - ey);
        cap = max(cap, c);
    }
    return cap;
}

__global__ void __launch_bounds__(NT, 1)
k_sim(const float* __restrict__ sig,  const float* __restrict__ Bext,
      const float* __restrict__ Msat, const float* __restrict__ src,
      const float* __restrict__ pmask, float* __restrict__ out)
{
    extern __shared__ __align__(16) float dyn[];
    float (*SA)[EXTP] = reinterpret_cast<float(*)[EXTP]>(dyn);
    float (*SB)[EXTP] = reinterpret_cast<float(*)[EXTP]>(dyn + 3*EXTP);
    __shared__ float redA[NT/32], redB[NT/32];
    __shared__ float s_pminv;
    __shared__ float s_sig[TSTEPS];
    __shared__ short sOwner[NSTRIPS];
    __shared__ signed char sClass[NSTRIPS];

    const int tid = threadIdx.x;
    const int tx = (int)blockIdx.y, ty = (int)blockIdx.x;
    const int gx0 = tx*IXt - Hh, gy0 = ty*IYt - Hh;
    const bool cta0 = (tx == 0 && ty == 0);

    // ---- deterministic cap-ordered thread->strip mapping ----
    sClass[tid] = (signed char)strip_cap(tid / NSTR, tid % NSTR, gx0, gy0);
    sOwner[tid] = -1;
    __syncthreads();
    {
        int myc = sClass[tid];
        if (myc >= 0) {
            int r = 0;
            for (int s2 = 0; s2 < NSTRIPS; ++s2) {
                int cs = sClass[s2];
                r += (cs > myc) || (cs == myc && s2 < tid);
            }
            sOwner[r] = (short)tid;
        }
    }
    __syncthreads();
    const int myStrip = sOwner[tid];
    const bool live = (myStrip >= 0);
    const int ex = live ? myStrip / NSTR : 0;
    const int sy = live ? myStrip % NSTR : 0;
    const int scap = live ? (int)sClass[myStrip] : -1;

    const int gx  = gx0 + ex;
    const int gyb = gy0 + SW*sy;
    const int eP  = ex*EYtP + 4*sy;

    const int exm = (ex == 0       || gx <= 0)       ? ex : ex - 1;
    const int exq = (ex == EXt - 1 || gx >= NXg - 1) ? ex : ex + 1;
    const int emb = exm*EYtP + 4*sy;
    const int epb = exq*EYtP + 4*sy;
    const int yLs = (sy == 0)        ? eP     : eP - 2;   // prev strip's j=2
    const int yRs = (sy == NSTR - 1) ? eP + 2 : eP + 4;   // next strip's j=0

    // per-cell flags / addresses
    bool intj[SW], mg0[SW], mgN[SW];
    int  gj[SW];
    const int tx0 = tx*IXt, ty0 = ty*IYt;
    int anyint = 0;
    #pragma unroll
    for (int j = 0; j < SW; j++) {
        int gy = gyb + j;
        intj[j] = live && gx >= tx0 && gx < tx0 + IXt && gy >= ty0 && gy < ty0 + IYt;
        if (intj[j]) anyint = 1;
        mg0[j] = (gy == 0);          // Neumann: y- neighbor = self
        mgN[j] = (gy == NYg - 1);    // Neumann: y+ neighbor = self
        int gxc = min(max(gx, 0), NXg - 1);
        int gyc = min(max(gy, 0), NYg - 1);
        gj[j] = gxc*NYg + gyc;
    }

    const float MU0f    = (float)(4e-7 * 3.14159265358979323846);
    const float TWO_A   = (float)(2.0 * 3.65e-12);
    const float INV_DX2 = (float)(1.0 / (50e-9 * 50e-9));
    const double hd  = 1.7595e11 * 5e-12;
    const float c05  = (float)(0.5 * hd);
    const float cfl  = (float)hd;
    const float h6   = (float)(hd / 6.0);
    const float i_rx = (float)(1.0 / (1.0 + 0.5 * 0.5));
    const float i_rn = (float)(1.0 / (1.0 + 0.01 * 0.01));
    const float nC05_rx = -(c05 * i_rx), nCfl_rx = -(cfl * i_rx), nH6_rx = -(h6 * i_rx);
    const float nC05_rn = -(c05 * i_rn), nCfl_rn = -(cfl * i_rn), nH6_rn = -(h6 * i_rn);

    // -------- static per-cell constants (registers, whole run) --------
    float rB0[SW], rB1[SW], rB2[SW], rS0[SW], rS1[SW], rS2[SW];
    float rCL[SW], rDg[SW], pmw[SW], m0x[SW];
    int anyp = 0;
    #pragma unroll
    for (int j = 0; j < SW; j++) {
        int g = gj[j];
        float ms = Msat[g];
        rCL[j] = (TWO_A / ms) * INV_DX2;
        rDg[j] = MU0f * ms;
        rB0[j] = Bext[0*NG + g]; rB1[j] = Bext[1*NG + g]; rB2[j] = Bext[2*NG + g];
        rS0[j] = src [0*NG + g]; rS1[j] = src [1*NG + g]; rS2[j] = src [2*NG + g];
        float pv = intj[j] ? pmask[g] : 0.f;
        pmw[j] = pv * ms;
        m0x[j] = 0.f;
        if (pv != 0.f) anyp = 1;
    }

    for (int i = tid; i < TSTEPS; i += NT) s_sig[i] = sig[i];
    if (cta0) {
        for (int i = tid; i < TSTEPS; i += NT) out[i] = 0.f;
        if (tid == 0)
            asm volatile("st.relaxed.gpu.u32 [%0], %1;" :: "l"(&g_count), "r"(0u) : "memory");
    }

    const int hasp = __syncthreads_or(anyp);
    if (hasp) {
        float s = 0.f;
        for (int i = tid; i < NG; i += NT) s += pmask[i];
        #pragma unroll
        for (int o = 16; o; o >>= 1) s += __shfl_down_sync(0xffffffffu, s, o);
        if ((tid & 31) == 0) redA[tid >> 5] = s;
        __syncthreads();
        if (tid < 32) {
            float v = (tid < NT/32) ? redA[tid] : 0.f;
            #pragma unroll
            for (int o = 8; o; o >>= 1) v += __shfl_down_sync(0xffffffffu, v, o);
            if (tid == 0) s_pminv = 1.f / v;
        }
    }

    unsigned lsense = 0;
    initbar(lsense);
    initbar(lsense);

    // m carried in registers; SA = state at pair start
    float mb0[SW], mb1[SW], mb2[SW];
    #pragma unroll
    for (int j = 0; j < SW; j++) { mb0[j] = 0.f; mb1[j] = 0.f; mb2[j] = 1.f; }
    if (live) {
        *(float4*)&SA[0][eP] = make_float4(0.f, 0.f, 0.f, 0.f);
        *(float4*)&SA[1][eP] = make_float4(0.f, 0.f, 0.f, 0.f);
        *(float4*)&SA[2][eP] = make_float4(1.f, 1.f, 1.f, 1.f);
    }
    __syncthreads();

    for (int p = 0; p < NPAIRS; ++p) {
        const bool  probe = (p >= RELAX/2);
        const int   ta    = 2*p - RELAX;                 // first step's signal index
        const float sv_a  = probe ? s_sig[ta]     : 0.f;
        const float sv_b  = probe ? s_sig[ta + 1] : 0.f;
        const float alpha = probe ? 0.01f : 0.5f;
        const float nC05  = probe ? nC05_rn : nC05_rx;
        const float nCfl  = probe ? nCfl_rn : nCfl_rx;
        const float nH6   = probe ? nH6_rn  : nH6_rx;
        const float* __restrict__ m_in  = g_m[(p + 1) & 1];
        float*       __restrict__ m_out = g_m[p & 1];

        // ---- halo refresh: all non-interior cells of live strips ----
        if (live && p > 0) {
            #pragma unroll
            for (int j = 0; j < SW; j++) {
                if (!intj[j]) {
                    float v0 = __ldcg(&m_in[0*NG + gj[j]]);
                    float v1 = __ldcg(&m_in[1*NG + gj[j]]);
                    float v2 = __ldcg(&m_in[2*NG + gj[j]]);
                    mb0[j] = v0; mb1[j] = v1; mb2[j] = v2;
                    SA[0][eP + j] = v0;
                    SA[1][eP + j] = v1;
                    SA[2][eP + j] = v2;
                }
            }
        }

        float tB0[SW], tB1[SW], tB2[SW];
        float st0[SW], st1[SW], st2[SW];
        float a0[SW], a1[SW], a2[SW];
        #pragma unroll
        for (int j = 0; j < SW; j++) {
            tB0[j] = fmaf(sv_a, rS0[j], rB0[j]);
            tB1[j] = fmaf(sv_a, rS1[j], rB1[j]);
            tB2[j] = fmaf(sv_a, rS2[j], rB2[j]);
            st0[j] = mb0[j]; st1[j] = mb1[j]; st2[j] = mb2[j];
            a0[j] = 0.f; a1[j] = 0.f; a2[j] = 0.f;
        }
        __syncthreads();

        // one RK substage. fin=true: fold final k, produce m (nH6), reset acc.
        auto stage = [&](const float (*__restrict__ S)[EXTP],
                         float (*__restrict__ D)[EXTP],
                         float nCoef, float w, bool fin) {
            float4 xm0 = *(const float4*)&S[0][emb];
            float4 xm1 = *(const float4*)&S[1][emb];
            float4 xm2 = *(const float4*)&S[2][emb];
            float4 xp0 = *(const float4*)&S[0][epb];
            float4 xp1 = *(const float4*)&S[1][epb];
            float4 xp2 = *(const float4*)&S[2][epb];
            float lo0 = S[0][yLs], lo1 = S[1][yLs], lo2 = S[2][yLs];
            float hi0 = S[0][yRs], hi1 = S[1][yRs], hi2 = S[2][yRs];
            // snapshot pre-stage state (register neighbors must be pre-update)
            float p0[SW] = {st0[0], st0[1], st0[2]};
            float p1[SW] = {st1[0], st1[1], st1[2]};
            float p2[SW] = {st2[0], st2[1], st2[2]};
            float XM0[SW] = {xm0.x, xm0.y, xm0.z};
            float XM1[SW] = {xm1.x, xm1.y, xm1.z};
            float XM2[SW] = {xm2.x, xm2.y, xm2.z};
            float XP0[SW] = {xp0.x, xp0.y, xp0.z};
            float XP1[SW] = {xp1.x, xp1.y, xp1.z};
            float XP2[SW] = {xp2.x, xp2.y, xp2.z};
            #pragma unroll
            for (int j = 0; j < SW; j++) {
                float mx = p0[j], my = p1[j], mz = p2[j];
                float yl0 = mg0[j] ? mx : ((j == 0) ? lo0 : p0[j-1]);
                float yl1 = mg0[j] ? my : ((j == 0) ? lo1 : p1[j-1]);
                float yl2 = mg0[j] ? mz : ((j == 0) ? lo2 : p2[j-1]);
                float yr0 = mgN[j] ? mx : ((j == SW-1) ? hi0 : p0[j+1]);
                float yr1 = mgN[j] ? my : ((j == SW-1) ? hi1 : p1[j+1]);
                float yr2 = mgN[j] ? mz : ((j == SW-1) ? hi2 : p2[j+1]);
                float l0 = XM0[j] + XP0[j] + yl0 + yr0 - 4.f*mx;
                float l1 = XM1[j] + XP1[j] + yl1 + yr1 - 4.f*my;
                float l2 = XM2[j] + XP2[j] + yl2 + yr2 - 4.f*mz;
                float Bx = fmaf(rCL[j], l0, tB0[j]);
                float By = fmaf(rCL[j], l1, tB1[j]);
                float Bz = fmaf(rCL[j], l2, tB2[j]) - rDg[j]*mz;
                float px = my*Bz - mz*By;
                float py = mz*Bx - mx*Bz;
                float pz = mx*By - my*Bx;
                float qx = my*pz - mz*py;
                float qy = mz*px - mx*pz;
                float qz = mx*py - my*px;
                float k0 = fmaf(alpha, qx, px);   // k' (sign/inv1a folded in coefs)
                float k1 = fmaf(alpha, qy, py);
                float k2 = fmaf(alpha, qz, pz);
                if (!fin) {
                    a0[j] = fmaf(w, k0, a0[j]);
                    a1[j] = fmaf(w, k1, a1[j]);
                    a2[j] = fmaf(w, k2, a2[j]);
                    st0[j] = fmaf(nCoef, k0, mb0[j]);
                    st1[j] = fmaf(nCoef, k1, mb1[j]);
                    st2[j] = fmaf(nCoef, k2, mb2[j]);
                } else {
                    float m0n = fmaf(nH6, a0[j] + k0, mb0[j]);
                    float m1n = fmaf(nH6, a1[j] + k1, mb1[j]);
                    float m2n = fmaf(nH6, a2[j] + k2, mb2[j]);
                    mb0[j] = m0n; mb1[j] = m1n; mb2[j] = m2n;
                    st0[j] = m0n; st1[j] = m1n; st2[j] = m2n;
                    a0[j] = 0.f; a1[j] = 0.f; a2[j] = 0.f;
                }
            }
            *(float4*)&D[0][eP] = make_float4(st0[0], st0[1], st0[2], st0[2]);
            *(float4*)&D[1][eP] = make_float4(st1[0], st1[1], st1[2], st1[2]);
            *(float4*)&D[2][eP] = make_float4(st2[0], st2[1], st2[2], st2[2]);
        };

        // ---- first RK4 step (stages 1..4), ends with m1 published to SA ----
        if (scap >= 1) stage(SA, SB, nC05, 1.f, false);
        __syncthreads();
        if (scap >= 2) stage(SB, SA, nC05, 2.f, false);
        __syncthreads();
        if (scap >= 3) stage(SA, SB, nCfl, 2.f, false);
        __syncthreads();
        if (scap >= 4) stage(SB, SA, 0.f, 1.f, true);    // m1 -> mb, SA
        __syncthreads();

        // mid-pair probe (m1) into part_a; reduce later
        float part_a = 0.f;
        if (probe && anyint) {
            #pragma unroll
            for (int j = 0; j < SW; j++)
                part_a += (mb0[j] - m0x[j]) * pmw[j];
        }

        // second half field (signal of step ta+1)
        #pragma unroll
        for (int j = 0; j < SW; j++) {
            tB0[j] = fmaf(sv_b, rS0[j], rB0[j]);
            tB1[j] = fmaf(sv_b, rS1[j], rB1[j]);
            tB2[j] = fmaf(sv_b, rS2[j], rB2[j]);
        }

        // ---- second RK4 step (stages 5..8) ----
        if (scap >= 5) stage(SA, SB, nC05, 1.f, false);
        __syncthreads();
        if (scap >= 6) stage(SB, SA, nC05, 2.f, false);
        __syncthreads();
        if (scap >= 7) stage(SA, SB, nCfl, 2.f, false);
        __syncthreads();
        if (scap >= 8) stage(SB, SA, 0.f, 1.f, true);    // m2 -> mb, SA

        // ---- stores + end-pair probe ----
        float part_b = 0.f;
        if (anyint) {
            #pragma unroll
            for (int j = 0; j < SW; j++) {
                if (intj[j]) {
                    __stcg(&m_out[0*NG + gj[j]], mb0[j]);
                    __stcg(&m_out[1*NG + gj[j]], mb1[j]);
                    __stcg(&m_out[2*NG + gj[j]], mb2[j]);
                    if (p == RELAX/2 - 1) m0x[j] = mb0[j];   // relaxed state (x)
                    if (probe) part_b += (mb0[j] - m0x[j]) * pmw[j];
                }
            }
        }

        if (p == NPAIRS - 1) {
            if (probe && hasp) {
                #pragma unroll
                for (int o = 16; o; o >>= 1) {
                    part_a += __shfl_down_sync(0xffffffffu, part_a, o);
                    part_b += __shfl_down_sync(0xffffffffu, part_b, o);
                }
                if ((tid & 31) == 0) { redA[tid >> 5] = part_a; redB[tid >> 5] = part_b; }
                __syncthreads();
                if (tid < 32) {
                    float va = (tid < NT/32) ? redA[tid] : 0.f;
                    float vb = (tid < NT/32) ? redB[tid] : 0.f;
                    #pragma unroll
                    for (int o = 8; o; o >>= 1) {
                        va += __shfl_down_sync(0xffffffffu, va, o);
                        vb += __shfl_down_sync(0xffffffffu, vb, o);
                    }
                    if (tid == 0) {
                        atomicAdd(&out[ta],     va * s_pminv);
                        atomicAdd(&out[ta + 1], vb * s_pminv);
                    }
                }
            }
            break;
        }

        // ---- arrive (release covers all threads' stores via prior sync) ----
        __syncthreads();
        if (tid == 0)
            asm volatile("red.add.release.gpu.u32 [%0], %1;"
                         :: "l"(&g_count), "r"(1u) : "memory");

        // ---- probe reductions overlap other CTAs' spin ----
        if (probe && hasp) {
            #pragma unroll
            for (int o = 16; o; o >>= 1) {
                part_a += __shfl_down_sync(0xffffffffu, part_a, o);
                part_b += __shfl_down_sync(0xffffffffu, part_b, o);
            }
            if ((tid & 31) == 0) { redA[tid >> 5] = part_a; redB[tid >> 5] = part_b; }
            __syncthreads();
            if (tid < 32) {
                float va = (tid < NT/32) ? redA[tid] : 0.f;
                float vb = (tid < NT/32) ? redB[tid] : 0.f;
                #pragma unroll
                for (int o = 8; o; o >>= 1) {
                    va += __shfl_down_sync(0xffffffffu, va, o);
                    vb += __shfl_down_sync(0xffffffffu, vb, o);
                }
                if (tid == 0) {
                    atomicAdd(&out[ta],     va * s_pminv);
                    atomicAdd(&out[ta + 1], vb * s_pminv);
                }
            }
        }

        // ---- wait: every CTA polls the monotonic counter directly ----
        if (tid == 0) {
            const unsigned need = (unsigned)(p + 1) * (unsigned)NCTA;
            unsigned v;
            do {
                asm volatile("ld.acquire.gpu.u32 %0, [%1];" : "=r"(v) : "l"(&g_count) : "memory");
            } while (v < need);
        }
        __syncthreads();
    }
}

// ---------------- host launcher: ONE graph node ----------------
extern "C" void kernel_launch(void* const* d_in, const int* in_sizes, int n_in,
                              void* d_out, int out_size)
{
    const float* sig   = (const float*)d_in[0];
    const float* Bext  = (const float*)d_in[1];
    const float* Msat  = (const float*)d_in[2];
    const float* src   = (const float*)d_in[3];
    const float* pmask = (const float*)d_in[4];
    float* out = (float*)d_out;

    cudaFuncSetAttribute(k_sim, cudaFuncAttributeMaxDynamicSharedMemorySize, DYN_SMEM);
    dim3 grid(NBX, NBY);
    k_sim<<<grid, NT, DYN_SMEM>>>(sig, Bext, Msat, src, pmask, out);
}